// round 1
// baseline (speedup 1.0000x reference)
#include <cuda_runtime.h>
#include <math.h>

// TopKTokenChoiceRouter: logits = x(T,4096) @ W(64,4096)^T ; softmax ; top-2.
// Output layout guess: [weights (T,2) fp32][indices (T,2) as fp32], concat, row-major.

#define HS      4096
#define NEXP    64
#define TM      64          // tokens per CTA
#define KC      32          // k-chunk
#define NT      (HS / KC)   // 128 chunks
#define THREADS 256

__global__ __launch_bounds__(THREADS, 1)
void router_kernel(const float* __restrict__ x,
                   const float* __restrict__ W,
                   float* __restrict__ out,
                   int T)
{
    // padded rows (stride KC+1=33) -> <=2-way bank conflicts on reads, ~0 on stores
    __shared__ float xs[2][TM][KC + 1];
    __shared__ float ws[2][NEXP][KC + 1];

    const int tid  = threadIdx.x;
    const int tx   = tid & 15;        // token-group 0..15 (4 tokens each)
    const int ty   = tid >> 4;        // expert-group 0..15 (4 experts each)
    const int tok0 = blockIdx.x * TM;

    const int lrow = tid >> 3;        // 0..31 (row for tile loads)
    const int lcol = tid & 7;         // 0..7  (float4 slot, 8*4 = 32 floats/row)

    float acc[4][4];
#pragma unroll
    for (int i = 0; i < 4; i++)
#pragma unroll
        for (int j = 0; j < 4; j++) acc[i][j] = 0.0f;

    auto load_tiles = [&](int kt, int b) {
        const int kb = kt * KC;
#pragma unroll
        for (int p = 0; p < 2; p++) {
            const int r = lrow + p * 32;           // 0..63: token row AND expert row
            // x tile: 64 tokens x 32 k   (coalesced 128B per row-group)
            const float4 vx = *(const float4*)&x[(long)(tok0 + r) * HS + kb + lcol * 4];
            xs[b][r][lcol * 4 + 0] = vx.x;
            xs[b][r][lcol * 4 + 1] = vx.y;
            xs[b][r][lcol * 4 + 2] = vx.z;
            xs[b][r][lcol * 4 + 3] = vx.w;
            // W tile: 64 experts x 32 k
            const float4 vw = *(const float4*)&W[(long)r * HS + kb + lcol * 4];
            ws[b][r][lcol * 4 + 0] = vw.x;
            ws[b][r][lcol * 4 + 1] = vw.y;
            ws[b][r][lcol * 4 + 2] = vw.z;
            ws[b][r][lcol * 4 + 3] = vw.w;
        }
    };

    load_tiles(0, 0);
    __syncthreads();

    for (int kt = 0; kt < NT; kt++) {
        const int b = kt & 1;
        if (kt + 1 < NT) load_tiles(kt + 1, b ^ 1);   // prefetch into other buffer

#pragma unroll 8
        for (int k = 0; k < KC; k++) {
            float xv[4], wv[4];
#pragma unroll
            for (int i = 0; i < 4; i++) xv[i] = xs[b][tx * 4 + i][k];
#pragma unroll
            for (int j = 0; j < 4; j++) wv[j] = ws[b][ty * 4 + j][k];
#pragma unroll
            for (int i = 0; i < 4; i++)
#pragma unroll
                for (int j = 0; j < 4; j++)
                    acc[i][j] = fmaf(xv[i], wv[j], acc[i][j]);
        }
        __syncthreads();
    }

    // ---- epilogue: stash logits in (reused) smem, then softmax + top-2 ----
    float* lsm = &xs[0][0][0];        // need 64*65 = 4160 floats <= 2*64*33 = 4224
#pragma unroll
    for (int i = 0; i < 4; i++)
#pragma unroll
        for (int j = 0; j < 4; j++)
            lsm[(tx * 4 + i) * 65 + (ty * 4 + j)] = acc[i][j];
    __syncthreads();

    if (tid < TM) {
        const int t = tid;
        float m1 = -INFINITY, m2 = -INFINITY;
        int   i1 = 0, i2 = 0;
        // ascending scan with strict '>' matches lax.top_k tie-breaking (lower index wins)
#pragma unroll 8
        for (int e = 0; e < NEXP; e++) {
            const float v = lsm[t * 65 + e];
            if (v > m1) { m2 = m1; i2 = i1; m1 = v; i1 = e; }
            else if (v > m2) { m2 = v; i2 = e; }
        }
        float s = 0.0f;
#pragma unroll 8
        for (int e = 0; e < NEXP; e++)
            s += __expf(lsm[t * 65 + e] - m1);
        const float inv = 1.0f / s;
        const float w1 = inv;                    // exp(0)/s
        const float w2 = __expf(m2 - m1) * inv;

        const int tg = tok0 + t;
        out[2 * tg + 0] = w1;
        out[2 * tg + 1] = w2;
        out[2 * T + 2 * tg + 0] = (float)i1;
        out[2 * T + 2 * tg + 1] = (float)i2;
    }
}

extern "C" void kernel_launch(void* const* d_in, const int* in_sizes, int n_in,
                              void* d_out, int out_size)
{
    const float* x = (const float*)d_in[0];
    const float* W = (const float*)d_in[1];
    int sx = in_sizes[0];
    if (n_in >= 2 && in_sizes[0] < in_sizes[1]) {   // defensive: x is the big one
        x = (const float*)d_in[1];
        W = (const float*)d_in[0];
        sx = in_sizes[1];
    }
    const int T = sx / HS;                          // 8192 tokens
    router_kernel<<<T / TM, THREADS>>>(x, W, (float*)d_out, T);
}